// round 13
// baseline (speedup 1.0000x reference)
#include <cuda_runtime.h>

// Problem constants (fixed by the dataset)
#define BB 16
#define TT 128
#define UU 64
#define VV 1024
#define CELLS (BB * TT * UU)      // 131072
#define NEGF   (-1e30f)
#define LOG2EF 1.4426950408889634f
#define LN2F   0.6931471805599453f

// Scratch (allocation-free rule: __device__ globals)
// lp tables stored PRE-SCALED by log2(e) (log2-domain DP).
__device__ float g_lpb[CELLS];    // lp_blank * log2e
__device__ float g_lpl[CELLS];    // lp_label * log2e (u < UU-1 valid)
__device__ float g_cost[BB];
__device__ int   g_ticket;        // last-block-done counter (zero-init; winner resets)
__device__ int   g_done[BB];      // per-batch lse completion counters (self-resetting)

__device__ __forceinline__ float fast_ex2(float x) {
    float r; asm("ex2.approx.ftz.f32 %0, %1;" : "=f"(r) : "f"(x)); return r;
}
__device__ __forceinline__ float fast_lg2(float x) {
    float r; asm("lg2.approx.ftz.f32 %0, %1;" : "=f"(r) : "f"(x)); return r;
}
__device__ __forceinline__ float lae2(float a, float b) {
    float M = fmaxf(a, b);
    return M + fast_lg2(fast_ex2(a - M) + fast_ex2(b - M));
}
// LAE3 with median trick: the max term contributes ex2(0)=1 exactly.
__device__ __forceinline__ float lae3(float x, float y, float z) {
    float lo = fminf(x, y), hi = fmaxf(x, y);
    float M  = fmaxf(hi, z);
    float e  = 1.0f + fast_ex2(lo - M) + fast_ex2(fminf(hi, z) - M);
    return M + fast_lg2(e);
}

// ---------------------------------------------------------------------------
// Packed-pair exp via fma.rn.f32x2 (FFMA2, sm_103a PTX-only).
// ---------------------------------------------------------------------------
__device__ __forceinline__ unsigned long long packf2(float a, float b) {
    unsigned long long r;
    asm("mov.b64 %0, {%1, %2};" : "=l"(r) : "f"(a), "f"(b));
    return r;
}
__device__ __forceinline__ void fexp_x2(unsigned long long X, float& r0, float& r1) {
    const float C1f   = 1.4426950408889634f;
    const float MAGIC = 12582912.0f;           // 1.5 * 2^23
    unsigned long long c1  = packf2(C1f, C1f);
    unsigned long long mg  = packf2(MAGIC, MAGIC);
    unsigned long long n1  = packf2(-1.0f, -1.0f);
    unsigned long long k4  = packf2(0.0096181291076285f, 0.0096181291076285f);
    unsigned long long k3  = packf2(0.0555041086648216f, 0.0555041086648216f);
    unsigned long long k2  = packf2(0.2402265069591007f, 0.2402265069591007f);
    unsigned long long k1  = packf2(0.6931471805599453f, 0.6931471805599453f);
    unsigned long long one = packf2(1.0f, 1.0f);

    unsigned long long z, d, f, p;
    asm("fma.rn.f32x2 %0, %1, %2, %3;" : "=l"(z) : "l"(X), "l"(c1), "l"(mg));
    asm("fma.rn.f32x2 %0, %1, %2, %3;" : "=l"(d) : "l"(z), "l"(n1), "l"(mg));  // MAGIC - z
    asm("fma.rn.f32x2 %0, %1, %2, %3;" : "=l"(f) : "l"(X), "l"(c1), "l"(d));
    asm("fma.rn.f32x2 %0, %1, %2, %3;" : "=l"(p) : "l"(f), "l"(k4), "l"(k3));
    asm("fma.rn.f32x2 %0, %1, %2, %3;" : "=l"(p) : "l"(f), "l"(p),  "l"(k2));
    asm("fma.rn.f32x2 %0, %1, %2, %3;" : "=l"(p) : "l"(f), "l"(p),  "l"(k1));
    asm("fma.rn.f32x2 %0, %1, %2, %3;" : "=l"(p) : "l"(f), "l"(p),  "l"(one));

    int p0, p1, z0, z1;
    asm("mov.b64 {%0, %1}, %2;" : "=r"(p0), "=r"(p1) : "l"(p));
    asm("mov.b64 {%0, %1}, %2;" : "=r"(z0), "=r"(z1) : "l"(z));
    r0 = __int_as_float(p0 + (z0 << 23));      // 2^k splice (exact)
    r1 = __int_as_float(p1 + (z1 << 23));
}

// ---------------------------------------------------------------------------
// Phase 1: one warp per (b,t,u) cell; 8 front-batched float4 streaming loads.
// At the LTS/DRAM cap (~6.86 TB/s). Each block signals its batch's readiness
// counter at exit so the PDL-resident dp block for that batch can start
// without waiting for the whole grid.
// ---------------------------------------------------------------------------
__global__ void __launch_bounds__(256) lse_kernel(const float* __restrict__ acts,
                                                  const int*   __restrict__ labels) {
#if __CUDA_ARCH__ >= 900
    if (threadIdx.x == 0) cudaTriggerProgrammaticLaunchCompletion();
#endif
    int warp = blockIdx.x * 8 + (threadIdx.x >> 5);
    int lane = threadIdx.x & 31;
    const float*  base = acts + (size_t)warp * VV;
    const float4* p4   = (const float4*)base;

    float4 v[8];
#pragma unroll
    for (int i = 0; i < 8; i++)
        v[i] = __ldcs(&p4[i * 32 + lane]);

    float blank = v[0].x;                      // valid on lane 0 only
    float s0 = 0.f, s1 = 0.f, s2 = 0.f, s3 = 0.f;
#pragma unroll
    for (int i = 0; i < 8; i++) {
        float e0, e1, e2, e3;
        fexp_x2(packf2(v[i].x, v[i].y), e0, e1);
        fexp_x2(packf2(v[i].z, v[i].w), e2, e3);
        s0 += e0; s1 += e1; s2 += e2; s3 += e3;
    }
    float s = (s0 + s1) + (s2 + s3);
#pragma unroll
    for (int o = 16; o; o >>= 1)
        s += __shfl_xor_sync(0xffffffffu, s, o);

    float lse2 = fast_lg2(s);                  // log2-domain lse

    if (lane == 0) {
        g_lpb[warp] = fmaf(blank, LOG2EF, -lse2);
        int u = warp & (UU - 1);
        if (u < UU - 1) {
            int b   = warp >> 13;
            int lab = labels[b * (UU - 1) + u];
            g_lpl[warp] = fmaf(base[lab], LOG2EF, -lse2);
        }
    }

    // Per-batch readiness: all 8 cells of this block are in one batch
    // (1024 blocks per batch, aligned).
    __syncthreads();
    if (threadIdx.x == 0) {
        __threadfence();
        atomicAdd(&g_done[blockIdx.x >> 10], 1);
    }
}

// ---------------------------------------------------------------------------
// Phase 2+3: BIDIRECTIONAL 2-diagonal-fused DP, one block per batch, made
// resident early via PDL. Each block waits ONLY on its own batch's 1024 lse
// blocks (per-batch counter), so batches 0..14 run fully overlapped with the
// lse stream; only the last batch's dp sits on the tail.
//  warp 0: forward alpha, 48 super-steps, diag 0 -> 96
//  warp 1: backward beta, 47 super-steps, diag 190 -> 96
//  meet:   loglike = LAE_u(alpha[96-u,u] + beta[96-u,u])
// ---------------------------------------------------------------------------
#define SF 48
#define SB 47

__global__ void __launch_bounds__(256) dp_kernel(float* __restrict__ out) {
    int b = blockIdx.x;
    extern __shared__ float sm[];
    float*  s_lpb  = sm;
    float*  s_lpl  = sm + 8192;
    float4* FW     = (float4*)(sm + 16384);
    float4* BW     = (float4*)(sm + 29184);
    float*  s_meet = sm + 41728;
    int tid = threadIdx.x;

    // Wait for THIS batch's lse blocks only (acquire via fence after poll).
    if (tid == 0) {
        volatile int* dc = &g_done[b];
        while (*dc < 1024) { }
        __threadfence();
        *dc = 0;                               // sole reader resets for next replay
    }
    __syncthreads();

    // Stage lp tables (float4, front-batched LDG).
    {
        const float4* gb = (const float4*)(g_lpb + b * TT * UU);
        const float4* gl = (const float4*)(g_lpl + b * TT * UU);
        float4* sb_ = (float4*)s_lpb;
        float4* sl_ = (float4*)s_lpl;
        float4 rb[8], rl[8];
#pragma unroll
        for (int i = 0; i < 8; i++) {
            rb[i] = __ldcg(&gb[i * 256 + tid]);
            rl[i] = __ldcg(&gl[i * 256 + tid]);
        }
#pragma unroll
        for (int i = 0; i < 8; i++) {
            sb_[i * 256 + tid] = rb[i];
            sl_[i * 256 + tid] = rl[i];
        }
    }
    __syncthreads();

    // ---- forward weights: j = s*64+u, s in [1,48] ----
    for (int j = 64 + tid; j < (SF + 1) * 64; j += 256) {
        int s = j >> 6, u = j & 63;
        int t = 2 * s - u;                     // in [-61, 96]
        int r0 = max(t, 0), r1 = max(t - 1, 0), r2 = max(t - 2, 0);
        int um1 = max(u - 1, 0), um2 = max(u - 2, 0);

        float b_r1u   = s_lpb[r1 * UU + u];
        float l_r0um1 = s_lpl[r0 * UU + um1];
        float A = s_lpb[r2 * UU + u] + b_r1u;
        float B = lae2(s_lpl[r1 * UU + um1] + b_r1u,
                       s_lpb[r1 * UU + um1] + l_r0um1);
        float C = s_lpl[r0 * UU + um2] + l_r0um1;
        if (u == 0) B = NEGF;
        if (u < 2)  C = NEGF;
        FW[j] = make_float4(A, B, C, 0.f);
    }
    // ---- backward weights: j = sb*64+u, sb in [1,47] ----
    for (int j = 64 + tid; j < (SB + 1) * 64; j += 256) {
        int sb = j >> 6, u = j & 63;
        int t = 190 - 2 * sb - u;              // >= 33 always; may be > 127
        int rt0 = min(t, TT - 1), rt1 = min(t + 1, TT - 1);
        int up1 = min(u + 1, UU - 1);

        float b00 = s_lpb[rt0 * UU + u],   b10 = s_lpb[rt1 * UU + u];
        float l00 = s_lpl[rt0 * UU + u],   l10 = s_lpl[rt1 * UU + u];
        float b01 = s_lpb[rt0 * UU + up1], l01 = s_lpl[rt0 * UU + up1];

        float A = b00 + b10;
        float B = lae2(b00 + l10, l00 + b01);
        float C = l00 + l01;
        if (u == 63) B = NEGF;
        if (u >= 62) C = NEGF;
        if (t > TT - 1) { A = NEGF; B = NEGF; C = NEGF; }
        BW[j] = make_float4(A, B, C, 0.f);
    }
    __syncthreads();

    int wid = tid >> 5, lane = tid & 31;
    int u_lo = lane * 2;

    if (wid == 0) {
        // ---------------- forward: 48 super-steps ----------------
        float a_lo = (lane == 0) ? 0.f : NEGF;
        float a_hi = NEGF;
        float nl_lo = __shfl_up_sync(0xffffffffu, a_lo, 1);
        float nl_hi = __shfl_up_sync(0xffffffffu, a_hi, 1);
        int W = 64 + u_lo;
        float4 w0 = FW[W], w1 = FW[W + 1];

#pragma unroll 2
        for (int s = 1; s < SF; s++) {
            float4 nw0 = FW[W + 64], nw1 = FW[W + 65];
            float n0 = lae3(a_lo + w0.x, nl_hi + w0.y, nl_lo + w0.z);
            float n1 = lae3(a_hi + w1.x, a_lo + w1.y, nl_hi + w1.z);
            a_lo = n0; a_hi = n1;
            nl_lo = __shfl_up_sync(0xffffffffu, a_lo, 1);
            nl_hi = __shfl_up_sync(0xffffffffu, a_hi, 1);
            w0 = nw0; w1 = nw1; W += 64;
        }
        {   // peel s = SF (no trailing shfl)
            float n0 = lae3(a_lo + w0.x, nl_hi + w0.y, nl_lo + w0.z);
            float n1 = lae3(a_hi + w1.x, a_lo + w1.y, nl_hi + w1.z);
            a_lo = n0; a_hi = n1;
        }
        s_meet[u_lo]     = a_lo;
        s_meet[u_lo + 1] = a_hi;
    } else if (wid == 1) {
        // ---------------- backward: 47 super-steps ----------------
        float b_lo = NEGF;
        float b_hi = (lane == 31) ? s_lpb[(TT - 1) * UU + (UU - 1)] : NEGF;
        float nr_lo = __shfl_down_sync(0xffffffffu, b_lo, 1);
        float nr_hi = __shfl_down_sync(0xffffffffu, b_hi, 1);
        int W = 64 + u_lo;
        float4 w0 = BW[W], w1 = BW[W + 1];

#pragma unroll 2
        for (int s = 1; s < SB; s++) {
            float4 nw0 = BW[W + 64], nw1 = BW[W + 65];
            float n0 = lae3(b_lo + w0.x, b_hi + w0.y, nr_lo + w0.z);
            float n1 = lae3(b_hi + w1.x, nr_lo + w1.y, nr_hi + w1.z);
            b_lo = n0; b_hi = n1;
            nr_lo = __shfl_down_sync(0xffffffffu, b_lo, 1);
            nr_hi = __shfl_down_sync(0xffffffffu, b_hi, 1);
            w0 = nw0; w1 = nw1; W += 64;
        }
        {   // peel s = SB
            float n0 = lae3(b_lo + w0.x, b_hi + w0.y, nr_lo + w0.z);
            float n1 = lae3(b_hi + w1.x, nr_lo + w1.y, nr_hi + w1.z);
            b_lo = n0; b_hi = n1;
        }
        s_meet[128 + u_lo]     = b_lo;
        s_meet[128 + u_lo + 1] = b_hi;
    }
    __syncthreads();

    // ---------------- combine on diag 96 + global mean ----------------
    if (wid == 0) {
        float v0 = s_meet[lane]      + s_meet[128 + lane];
        float v1 = s_meet[lane + 32] + s_meet[128 + lane + 32];
        float M = fmaxf(v0, v1);
#pragma unroll
        for (int o = 16; o; o >>= 1)
            M = fmaxf(M, __shfl_xor_sync(0xffffffffu, M, o));
        float e = fast_ex2(v0 - M) + fast_ex2(v1 - M);
#pragma unroll
        for (int o = 16; o; o >>= 1)
            e += __shfl_xor_sync(0xffffffffu, e, o);
        float ll2 = M + fast_lg2(e);           // log2-domain loglike

        int is_last = 0;
        if (lane == 0) {
            g_cost[b] = -ll2 * LN2F;
            __threadfence();
            is_last = (atomicAdd(&g_ticket, 1) == BB - 1);
        }
        is_last = __shfl_sync(0xffffffffu, is_last, 0);
        if (is_last) {
            float v = (lane < BB) ? __ldcg(&g_cost[lane]) : 0.f;
#pragma unroll
            for (int o = 16; o; o >>= 1)
                v += __shfl_xor_sync(0xffffffffu, v, o);
            if (lane == 0) {
                out[0] = v * (1.0f / BB);
                g_ticket = 0;                  // reset for next graph replay
            }
        }
    }
}

extern "C" void kernel_launch(void* const* d_in, const int* in_sizes, int n_in,
                              void* d_out, int out_size) {
    const float* acts   = (const float*)d_in[0];
    const int*   labels = (const int*)d_in[1];

    const int smem_bytes = 41984 * (int)sizeof(float);   // 167936
    cudaFuncSetAttribute(dp_kernel, cudaFuncAttributeMaxDynamicSharedMemorySize,
                         smem_bytes);

    lse_kernel<<<CELLS / 8, 256>>>(acts, labels);

    // PDL launch: dp blocks become resident while lse streams; ordering is
    // provided by the per-batch g_done handshake inside dp_kernel.
    cudaLaunchConfig_t cfg = {};
    cfg.gridDim         = dim3(BB, 1, 1);
    cfg.blockDim        = dim3(256, 1, 1);
    cfg.dynamicSmemBytes = smem_bytes;
    cfg.stream          = 0;
    cudaLaunchAttribute attr[1];
    attr[0].id = cudaLaunchAttributeProgrammaticStreamSerialization;
    attr[0].val.programmaticStreamSerializationAllowed = 1;
    cfg.attrs    = attr;
    cfg.numAttrs = 1;
    cudaLaunchKernelEx(&cfg, dp_kernel, (float*)d_out);
}

// round 14
// speedup vs baseline: 1.0297x; 1.0297x over previous
#include <cuda_runtime.h>

// Problem constants (fixed by the dataset)
#define BB 16
#define TT 128
#define UU 64
#define VV 1024
#define CELLS (BB * TT * UU)      // 131072
#define NEGF   (-1e30f)
#define LOG2EF 1.4426950408889634f
#define LN2F   0.6931471805599453f

// Scratch (allocation-free rule: __device__ globals)
// lp tables stored PRE-SCALED by log2(e) (log2-domain DP).
__device__ float g_lpb[CELLS];    // lp_blank * log2e
__device__ float g_lpl[CELLS];    // lp_label * log2e (u < UU-1 valid)
__device__ float g_cost[BB];
__device__ int   g_ticket;        // last-block-done counter (zero-init; winner resets)

__device__ __forceinline__ float fast_ex2(float x) {
    float r; asm("ex2.approx.ftz.f32 %0, %1;" : "=f"(r) : "f"(x)); return r;
}
__device__ __forceinline__ float fast_lg2(float x) {
    float r; asm("lg2.approx.ftz.f32 %0, %1;" : "=f"(r) : "f"(x)); return r;
}
// lae2 with median trick: max term contributes ex2(0)=1 exactly -> 2 MUFU.
__device__ __forceinline__ float lae2(float a, float b) {
    float M = fmaxf(a, b), m = fminf(a, b);
    return M + fast_lg2(1.0f + fast_ex2(m - M));
}
// LAE3 with median trick: the max term contributes ex2(0)=1 exactly.
__device__ __forceinline__ float lae3(float x, float y, float z) {
    float lo = fminf(x, y), hi = fmaxf(x, y);
    float M  = fmaxf(hi, z);
    float e  = 1.0f + fast_ex2(lo - M) + fast_ex2(fminf(hi, z) - M);
    return M + fast_lg2(e);
}

// ---------------------------------------------------------------------------
// Packed-pair exp via fma.rn.f32x2 (FFMA2, sm_103a PTX-only).
// ---------------------------------------------------------------------------
__device__ __forceinline__ unsigned long long packf2(float a, float b) {
    unsigned long long r;
    asm("mov.b64 %0, {%1, %2};" : "=l"(r) : "f"(a), "f"(b));
    return r;
}
__device__ __forceinline__ void fexp_x2(unsigned long long X, float& r0, float& r1) {
    const float C1f   = 1.4426950408889634f;
    const float MAGIC = 12582912.0f;           // 1.5 * 2^23
    unsigned long long c1  = packf2(C1f, C1f);
    unsigned long long mg  = packf2(MAGIC, MAGIC);
    unsigned long long n1  = packf2(-1.0f, -1.0f);
    unsigned long long k4  = packf2(0.0096181291076285f, 0.0096181291076285f);
    unsigned long long k3  = packf2(0.0555041086648216f, 0.0555041086648216f);
    unsigned long long k2  = packf2(0.2402265069591007f, 0.2402265069591007f);
    unsigned long long k1  = packf2(0.6931471805599453f, 0.6931471805599453f);
    unsigned long long one = packf2(1.0f, 1.0f);

    unsigned long long z, d, f, p;
    asm("fma.rn.f32x2 %0, %1, %2, %3;" : "=l"(z) : "l"(X), "l"(c1), "l"(mg));
    asm("fma.rn.f32x2 %0, %1, %2, %3;" : "=l"(d) : "l"(z), "l"(n1), "l"(mg));  // MAGIC - z
    asm("fma.rn.f32x2 %0, %1, %2, %3;" : "=l"(f) : "l"(X), "l"(c1), "l"(d));
    asm("fma.rn.f32x2 %0, %1, %2, %3;" : "=l"(p) : "l"(f), "l"(k4), "l"(k3));
    asm("fma.rn.f32x2 %0, %1, %2, %3;" : "=l"(p) : "l"(f), "l"(p),  "l"(k2));
    asm("fma.rn.f32x2 %0, %1, %2, %3;" : "=l"(p) : "l"(f), "l"(p),  "l"(k1));
    asm("fma.rn.f32x2 %0, %1, %2, %3;" : "=l"(p) : "l"(f), "l"(p),  "l"(one));

    int p0, p1, z0, z1;
    asm("mov.b64 {%0, %1}, %2;" : "=r"(p0), "=r"(p1) : "l"(p));
    asm("mov.b64 {%0, %1}, %2;" : "=r"(z0), "=r"(z1) : "l"(z));
    r0 = __int_as_float(p0 + (z0 << 23));      // 2^k splice (exact)
    r1 = __int_as_float(p1 + (z1 << 23));
}

// ---------------------------------------------------------------------------
// Phase 1: one warp per (b,t,u) cell; 8 front-batched float4 streaming loads.
// At the LTS/DRAM cap (~6.86 TB/s) — structurally done. Triggers PDL at
// entry so the dp kernel's blocks are dispatched while this streams.
// (R13 lesson: per-batch handshake overlap regressed — grid-sync PDL only.)
// ---------------------------------------------------------------------------
__global__ void __launch_bounds__(256) lse_kernel(const float* __restrict__ acts,
                                                  const int*   __restrict__ labels) {
#if __CUDA_ARCH__ >= 900
    if (threadIdx.x == 0) cudaTriggerProgrammaticLaunchCompletion();
#endif
    int warp = blockIdx.x * 8 + (threadIdx.x >> 5);
    int lane = threadIdx.x & 31;
    const float*  base = acts + (size_t)warp * VV;
    const float4* p4   = (const float4*)base;

    float4 v[8];
#pragma unroll
    for (int i = 0; i < 8; i++)
        v[i] = __ldcs(&p4[i * 32 + lane]);

    float blank = v[0].x;                      // valid on lane 0 only
    float s0 = 0.f, s1 = 0.f, s2 = 0.f, s3 = 0.f;
#pragma unroll
    for (int i = 0; i < 8; i++) {
        float e0, e1, e2, e3;
        fexp_x2(packf2(v[i].x, v[i].y), e0, e1);
        fexp_x2(packf2(v[i].z, v[i].w), e2, e3);
        s0 += e0; s1 += e1; s2 += e2; s3 += e3;
    }
    float s = (s0 + s1) + (s2 + s3);
#pragma unroll
    for (int o = 16; o; o >>= 1)
        s += __shfl_xor_sync(0xffffffffu, s, o);

    float lse2 = fast_lg2(s);                  // log2-domain lse

    if (lane == 0) {
        g_lpb[warp] = fmaf(blank, LOG2EF, -lse2);
        int u = warp & (UU - 1);
        if (u < UU - 1) {
            int b   = warp >> 13;
            int lab = labels[b * (UU - 1) + u];
            g_lpl[warp] = fmaf(base[lab], LOG2EF, -lse2);
        }
    }
}

// ---------------------------------------------------------------------------
// Phase 2+3: BIDIRECTIONAL 2-diagonal-fused DP, one block per batch, PDL
// grid-dependency sync (R12 committed best). This round: 512 threads per
// block (4 warps/SMSP on the weight build, halving its MUFU-issue time) and
// 2-MUFU lae2 in the build hot path.
//  warp 0: forward alpha, 48 super-steps, diag 0 -> 96
//  warp 1: backward beta, 47 super-steps, diag 190 -> 96
//  meet:   loglike = LAE_u(alpha[96-u,u] + beta[96-u,u])
// ---------------------------------------------------------------------------
#define SF 48
#define SB 47
#define DPT 512

__global__ void __launch_bounds__(DPT) dp_kernel(float* __restrict__ out) {
#if __CUDA_ARCH__ >= 900
    cudaGridDependencySynchronize();           // wait for lse stores to land
#endif
    int b = blockIdx.x;
    extern __shared__ float sm[];
    float*  s_lpb  = sm;
    float*  s_lpl  = sm + 8192;
    float4* FW     = (float4*)(sm + 16384);
    float4* BW     = (float4*)(sm + 29184);
    float*  s_meet = sm + 41728;
    int tid = threadIdx.x;

    // Stage lp tables (float4, front-batched LDG; 2048 f4 per table).
    {
        const float4* gb = (const float4*)(g_lpb + b * TT * UU);
        const float4* gl = (const float4*)(g_lpl + b * TT * UU);
        float4* sb_ = (float4*)s_lpb;
        float4* sl_ = (float4*)s_lpl;
        float4 rb[4], rl[4];
#pragma unroll
        for (int i = 0; i < 4; i++) {
            rb[i] = __ldcg(&gb[i * DPT + tid]);
            rl[i] = __ldcg(&gl[i * DPT + tid]);
        }
#pragma unroll
        for (int i = 0; i < 4; i++) {
            sb_[i * DPT + tid] = rb[i];
            sl_[i * DPT + tid] = rl[i];
        }
    }
    __syncthreads();

    // ---- forward weights: j = s*64+u, s in [1,48] ----
    for (int j = 64 + tid; j < (SF + 1) * 64; j += DPT) {
        int s = j >> 6, u = j & 63;
        int t = 2 * s - u;                     // in [-61, 96]
        int r0 = max(t, 0), r1 = max(t - 1, 0), r2 = max(t - 2, 0);
        int um1 = max(u - 1, 0), um2 = max(u - 2, 0);

        float b_r1u   = s_lpb[r1 * UU + u];
        float l_r0um1 = s_lpl[r0 * UU + um1];
        float A = s_lpb[r2 * UU + u] + b_r1u;
        float B = lae2(s_lpl[r1 * UU + um1] + b_r1u,
                       s_lpb[r1 * UU + um1] + l_r0um1);
        float C = s_lpl[r0 * UU + um2] + l_r0um1;
        if (u == 0) B = NEGF;
        if (u < 2)  C = NEGF;
        FW[j] = make_float4(A, B, C, 0.f);
    }
    // ---- backward weights: j = sb*64+u, sb in [1,47] ----
    for (int j = 64 + tid; j < (SB + 1) * 64; j += DPT) {
        int sb = j >> 6, u = j & 63;
        int t = 190 - 2 * sb - u;              // >= 33 always; may be > 127
        int rt0 = min(t, TT - 1), rt1 = min(t + 1, TT - 1);
        int up1 = min(u + 1, UU - 1);

        float b00 = s_lpb[rt0 * UU + u],   b10 = s_lpb[rt1 * UU + u];
        float l00 = s_lpl[rt0 * UU + u],   l10 = s_lpl[rt1 * UU + u];
        float b01 = s_lpb[rt0 * UU + up1], l01 = s_lpl[rt0 * UU + up1];

        float A = b00 + b10;
        float B = lae2(b00 + l10, l00 + b01);
        float C = l00 + l01;
        if (u == 63) B = NEGF;
        if (u >= 62) C = NEGF;
        if (t > TT - 1) { A = NEGF; B = NEGF; C = NEGF; }
        BW[j] = make_float4(A, B, C, 0.f);
    }
    __syncthreads();

    int wid = tid >> 5, lane = tid & 31;
    int u_lo = lane * 2;

    if (wid == 0) {
        // ---------------- forward: 48 super-steps ----------------
        float a_lo = (lane == 0) ? 0.f : NEGF;
        float a_hi = NEGF;
        float nl_lo = __shfl_up_sync(0xffffffffu, a_lo, 1);
        float nl_hi = __shfl_up_sync(0xffffffffu, a_hi, 1);
        int W = 64 + u_lo;
        float4 w0 = FW[W], w1 = FW[W + 1];

#pragma unroll 2
        for (int s = 1; s < SF; s++) {
            float4 nw0 = FW[W + 64], nw1 = FW[W + 65];
            float n0 = lae3(a_lo + w0.x, nl_hi + w0.y, nl_lo + w0.z);
            float n1 = lae3(a_hi + w1.x, a_lo + w1.y, nl_hi + w1.z);
            a_lo = n0; a_hi = n1;
            nl_lo = __shfl_up_sync(0xffffffffu, a_lo, 1);
            nl_hi = __shfl_up_sync(0xffffffffu, a_hi, 1);
            w0 = nw0; w1 = nw1; W += 64;
        }
        {   // peel s = SF (no trailing shfl)
            float n0 = lae3(a_lo + w0.x, nl_hi + w0.y, nl_lo + w0.z);
            float n1 = lae3(a_hi + w1.x, a_lo + w1.y, nl_hi + w1.z);
            a_lo = n0; a_hi = n1;
        }
        s_meet[u_lo]     = a_lo;
        s_meet[u_lo + 1] = a_hi;
    } else if (wid == 1) {
        // ---------------- backward: 47 super-steps ----------------
        float b_lo = NEGF;
        float b_hi = (lane == 31) ? s_lpb[(TT - 1) * UU + (UU - 1)] : NEGF;
        float nr_lo = __shfl_down_sync(0xffffffffu, b_lo, 1);
        float nr_hi = __shfl_down_sync(0xffffffffu, b_hi, 1);
        int W = 64 + u_lo;
        float4 w0 = BW[W], w1 = BW[W + 1];

#pragma unroll 2
        for (int s = 1; s < SB; s++) {
            float4 nw0 = BW[W + 64], nw1 = BW[W + 65];
            float n0 = lae3(b_lo + w0.x, b_hi + w0.y, nr_lo + w0.z);
            float n1 = lae3(b_hi + w1.x, nr_lo + w1.y, nr_hi + w1.z);
            b_lo = n0; b_hi = n1;
            nr_lo = __shfl_down_sync(0xffffffffu, b_lo, 1);
            nr_hi = __shfl_down_sync(0xffffffffu, b_hi, 1);
            w0 = nw0; w1 = nw1; W += 64;
        }
        {   // peel s = SB
            float n0 = lae3(b_lo + w0.x, b_hi + w0.y, nr_lo + w0.z);
            float n1 = lae3(b_hi + w1.x, nr_lo + w1.y, nr_hi + w1.z);
            b_lo = n0; b_hi = n1;
        }
        s_meet[128 + u_lo]     = b_lo;
        s_meet[128 + u_lo + 1] = b_hi;
    }
    __syncthreads();

    // ---------------- combine on diag 96 + global mean ----------------
    if (wid == 0) {
        float v0 = s_meet[lane]      + s_meet[128 + lane];
        float v1 = s_meet[lane + 32] + s_meet[128 + lane + 32];
        float M = fmaxf(v0, v1);
#pragma unroll
        for (int o = 16; o; o >>= 1)
            M = fmaxf(M, __shfl_xor_sync(0xffffffffu, M, o));
        float e = fast_ex2(v0 - M) + fast_ex2(v1 - M);
#pragma unroll
        for (int o = 16; o; o >>= 1)
            e += __shfl_xor_sync(0xffffffffu, e, o);
        float ll2 = M + fast_lg2(e);           // log2-domain loglike

        int is_last = 0;
        if (lane == 0) {
            g_cost[b] = -ll2 * LN2F;
            __threadfence();
            is_last = (atomicAdd(&g_ticket, 1) == BB - 1);
        }
        is_last = __shfl_sync(0xffffffffu, is_last, 0);
        if (is_last) {
            float v = (lane < BB) ? __ldcg(&g_cost[lane]) : 0.f;
#pragma unroll
            for (int o = 16; o; o >>= 1)
                v += __shfl_xor_sync(0xffffffffu, v, o);
            if (lane == 0) {
                out[0] = v * (1.0f / BB);
                g_ticket = 0;                  // reset for next graph replay
            }
        }
    }
}

extern "C" void kernel_launch(void* const* d_in, const int* in_sizes, int n_in,
                              void* d_out, int out_size) {
    const float* acts   = (const float*)d_in[0];
    const int*   labels = (const int*)d_in[1];

    const int smem_bytes = 41984 * (int)sizeof(float);   // 167936
    cudaFuncSetAttribute(dp_kernel, cudaFuncAttributeMaxDynamicSharedMemorySize,
                         smem_bytes);

    lse_kernel<<<CELLS / 8, 256>>>(acts, labels);

    // PDL launch: dp blocks dispatch while lse streams; the in-kernel grid
    // dependency sync provides the ordering.
    cudaLaunchConfig_t cfg = {};
    cfg.gridDim         = dim3(BB, 1, 1);
    cfg.blockDim        = dim3(DPT, 1, 1);
    cfg.dynamicSmemBytes = smem_bytes;
    cfg.stream          = 0;
    cudaLaunchAttribute attr[1];
    attr[0].id = cudaLaunchAttributeProgrammaticStreamSerialization;
    attr[0].val.programmaticStreamSerializationAllowed = 1;
    cfg.attrs    = attr;
    cfg.numAttrs = 1;
    cudaLaunchKernelEx(&cfg, dp_kernel, (float*)d_out);
}

// round 15
// speedup vs baseline: 1.0316x; 1.0019x over previous
#include <cuda_runtime.h>

// Problem constants (fixed by the dataset)
#define BB 16
#define TT 128
#define UU 64
#define VV 1024
#define CELLS (BB * TT * UU)      // 131072
#define NEGF   (-1e30f)
#define LOG2EF 1.4426950408889634f
#define LN2F   0.6931471805599453f

// Scratch (allocation-free rule: __device__ globals)
// lp tables stored PRE-SCALED by log2(e) (log2-domain DP).
__device__ float g_lpb[CELLS];    // lp_blank * log2e
__device__ float g_lpl[CELLS];    // lp_label * log2e (u < UU-1 valid; col 63 garbage, always NEG-guarded)
__device__ float g_cost[BB];
__device__ int   g_ticket;        // last-block-done counter (zero-init; winner resets)

__device__ __forceinline__ float fast_ex2(float x) {
    float r; asm("ex2.approx.ftz.f32 %0, %1;" : "=f"(r) : "f"(x)); return r;
}
__device__ __forceinline__ float fast_lg2(float x) {
    float r; asm("lg2.approx.ftz.f32 %0, %1;" : "=f"(r) : "f"(x)); return r;
}
// lae2/3/4 with median trick: the max term contributes ex2(0)=1 exactly.
__device__ __forceinline__ float lae2(float a, float b) {
    float M = fmaxf(a, b), m = fminf(a, b);
    return M + fast_lg2(1.0f + fast_ex2(m - M));
}
__device__ __forceinline__ float lae3(float x, float y, float z) {
    float lo = fminf(x, y), hi = fmaxf(x, y);
    float M  = fmaxf(hi, z);
    float e  = 1.0f + fast_ex2(lo - M) + fast_ex2(fminf(hi, z) - M);
    return M + fast_lg2(e);
}
__device__ __forceinline__ float lae4(float x, float y, float z, float w) {
    float m1 = fminf(x, y), M1 = fmaxf(x, y);
    float m2 = fminf(z, w), M2 = fmaxf(z, w);
    float M  = fmaxf(M1, M2);
    float m3 = fminf(M1, M2);
    float e  = 1.0f + fast_ex2(m1 - M) + fast_ex2(m2 - M) + fast_ex2(m3 - M);
    return M + fast_lg2(e);
}

// ---------------------------------------------------------------------------
// Packed-pair exp via fma.rn.f32x2 (FFMA2, sm_103a PTX-only).
// ---------------------------------------------------------------------------
__device__ __forceinline__ unsigned long long packf2(float a, float b) {
    unsigned long long r;
    asm("mov.b64 %0, {%1, %2};" : "=l"(r) : "f"(a), "f"(b));
    return r;
}
__device__ __forceinline__ void fexp_x2(unsigned long long X, float& r0, float& r1) {
    const float C1f   = 1.4426950408889634f;
    const float MAGIC = 12582912.0f;           // 1.5 * 2^23
    unsigned long long c1  = packf2(C1f, C1f);
    unsigned long long mg  = packf2(MAGIC, MAGIC);
    unsigned long long n1  = packf2(-1.0f, -1.0f);
    unsigned long long k4  = packf2(0.0096181291076285f, 0.0096181291076285f);
    unsigned long long k3  = packf2(0.0555041086648216f, 0.0555041086648216f);
    unsigned long long k2  = packf2(0.2402265069591007f, 0.2402265069591007f);
    unsigned long long k1  = packf2(0.6931471805599453f, 0.6931471805599453f);
    unsigned long long one = packf2(1.0f, 1.0f);

    unsigned long long z, d, f, p;
    asm("fma.rn.f32x2 %0, %1, %2, %3;" : "=l"(z) : "l"(X), "l"(c1), "l"(mg));
    asm("fma.rn.f32x2 %0, %1, %2, %3;" : "=l"(d) : "l"(z), "l"(n1), "l"(mg));  // MAGIC - z
    asm("fma.rn.f32x2 %0, %1, %2, %3;" : "=l"(f) : "l"(X), "l"(c1), "l"(d));
    asm("fma.rn.f32x2 %0, %1, %2, %3;" : "=l"(p) : "l"(f), "l"(k4), "l"(k3));
    asm("fma.rn.f32x2 %0, %1, %2, %3;" : "=l"(p) : "l"(f), "l"(p),  "l"(k2));
    asm("fma.rn.f32x2 %0, %1, %2, %3;" : "=l"(p) : "l"(f), "l"(p),  "l"(k1));
    asm("fma.rn.f32x2 %0, %1, %2, %3;" : "=l"(p) : "l"(f), "l"(p),  "l"(one));

    int p0, p1, z0, z1;
    asm("mov.b64 {%0, %1}, %2;" : "=r"(p0), "=r"(p1) : "l"(p));
    asm("mov.b64 {%0, %1}, %2;" : "=r"(z0), "=r"(z1) : "l"(z));
    r0 = __int_as_float(p0 + (z0 << 23));      // 2^k splice (exact)
    r1 = __int_as_float(p1 + (z1 << 23));
}

// ---------------------------------------------------------------------------
// Phase 1: one warp per (b,t,u) cell; 8 front-batched float4 streaming loads.
// At the DRAM cap (~6.86 TB/s) — structurally done. Triggers PDL at entry.
// ---------------------------------------------------------------------------
__global__ void __launch_bounds__(256) lse_kernel(const float* __restrict__ acts,
                                                  const int*   __restrict__ labels) {
#if __CUDA_ARCH__ >= 900
    if (threadIdx.x == 0) cudaTriggerProgrammaticLaunchCompletion();
#endif
    int warp = blockIdx.x * 8 + (threadIdx.x >> 5);
    int lane = threadIdx.x & 31;
    const float*  base = acts + (size_t)warp * VV;
    const float4* p4   = (const float4*)base;

    float4 v[8];
#pragma unroll
    for (int i = 0; i < 8; i++)
        v[i] = __ldcs(&p4[i * 32 + lane]);

    float blank = v[0].x;                      // valid on lane 0 only
    float s0 = 0.f, s1 = 0.f, s2 = 0.f, s3 = 0.f;
#pragma unroll
    for (int i = 0; i < 8; i++) {
        float e0, e1, e2, e3;
        fexp_x2(packf2(v[i].x, v[i].y), e0, e1);
        fexp_x2(packf2(v[i].z, v[i].w), e2, e3);
        s0 += e0; s1 += e1; s2 += e2; s3 += e3;
    }
    float s = (s0 + s1) + (s2 + s3);
#pragma unroll
    for (int o = 16; o; o >>= 1)
        s += __shfl_xor_sync(0xffffffffu, s, o);

    float lse2 = fast_lg2(s);                  // log2-domain lse

    if (lane == 0) {
        g_lpb[warp] = fmaf(blank, LOG2EF, -lse2);
        int u = warp & (UU - 1);
        if (u < UU - 1) {
            int b   = warp >> 13;
            int lab = labels[b * (UU - 1) + u];
            g_lpl[warp] = fmaf(base[lab], LOG2EF, -lse2);
        }
    }
}

// ---------------------------------------------------------------------------
// Phase 2+3: BIDIRECTIONAL 3-DIAGONAL-FUSED DP, one block per batch, PDL.
//  forward (warp 0): 32 super-steps on the t+u = 3s sublattice, diag 0 -> 96
//    alpha[t,u] = LAE4(a[t-3,u]+A, a[t-2,u-1]+B, a[t-1,u-2]+C, a[t,u-3]+D)
//    A/D = single 3-move path; B/C = LAE3 of the 3 interleavings.
//  backward (warp 1): 31 mirror super-steps diag 190 -> 97, then ONE plain
//    single-step 97 -> 96 (lpb/lpl read from the staged tables).
//  meet: loglike = LAE_u(alpha[96-u,u] + beta[96-u,u]).
// NEG sentinels absorb all out-of-lattice sources exactly; u-guards NEG the
// B/C/D weights near the u=0 / u=63 edges (also shields lpl column 63,
// which lse never writes).
// smem floats: lpb[0,8192) lpl[8192,16384) FW@16384 (33x64 f4 = 8448 f)
//              BW@24832 (32x64 f4 = 8192 f) meet@33024 (256) -> 33280 total
// ---------------------------------------------------------------------------
#define SF3 32
#define SB3 31
#define DPT 512

__global__ void __launch_bounds__(DPT) dp_kernel(float* __restrict__ out) {
#if __CUDA_ARCH__ >= 900
    cudaGridDependencySynchronize();           // wait for lse stores to land
#endif
    int b = blockIdx.x;
    extern __shared__ float sm[];
    float*  s_lpb  = sm;
    float*  s_lpl  = sm + 8192;
    float4* FW     = (float4*)(sm + 16384);    // rows s=0..32 (s in [1,32] used)
    float4* BW     = (float4*)(sm + 24832);    // rows m=0..31 (m in [1,31] used)
    float*  s_meet = sm + 33024;
    int tid = threadIdx.x;

    // Stage lp tables (float4, front-batched LDG; 2048 f4 per table).
    {
        const float4* gb = (const float4*)(g_lpb + b * TT * UU);
        const float4* gl = (const float4*)(g_lpl + b * TT * UU);
        float4* sb_ = (float4*)s_lpb;
        float4* sl_ = (float4*)s_lpl;
        float4 rb[4], rl[4];
#pragma unroll
        for (int i = 0; i < 4; i++) {
            rb[i] = __ldcg(&gb[i * DPT + tid]);
            rl[i] = __ldcg(&gl[i * DPT + tid]);
        }
#pragma unroll
        for (int i = 0; i < 4; i++) {
            sb_[i * DPT + tid] = rb[i];
            sl_[i * DPT + tid] = rl[i];
        }
    }
    __syncthreads();

    // ---- forward weights: j = s*64+u, s in [1,32] ----
    for (int j = 64 + tid; j < (SF3 + 1) * 64; j += DPT) {
        int s = j >> 6, u = j & 63;
        int t = 3 * s - u;                     // may be < 0 (dead cells)
        int t0 = min(max(t,     0), TT - 1);
        int t1 = min(max(t - 1, 0), TT - 1);
        int t2 = min(max(t - 2, 0), TT - 1);
        int t3 = min(max(t - 3, 0), TT - 1);
        int um1 = max(u - 1, 0), um2 = max(u - 2, 0), um3 = max(u - 3, 0);

        float A = s_lpb[t3 * UU + u] + s_lpb[t2 * UU + u] + s_lpb[t1 * UU + u];
        float B = lae3(
            s_lpl[t2 * UU + um1] + s_lpb[t2 * UU + u]   + s_lpb[t1 * UU + u],
            s_lpb[t2 * UU + um1] + s_lpl[t1 * UU + um1] + s_lpb[t1 * UU + u],
            s_lpb[t2 * UU + um1] + s_lpb[t1 * UU + um1] + s_lpl[t0 * UU + um1]);
        float C = lae3(
            s_lpb[t1 * UU + um2] + s_lpl[t0 * UU + um2] + s_lpl[t0 * UU + um1],
            s_lpl[t1 * UU + um2] + s_lpb[t1 * UU + um1] + s_lpl[t0 * UU + um1],
            s_lpl[t1 * UU + um2] + s_lpl[t1 * UU + um1] + s_lpb[t1 * UU + u]);
        float D = s_lpl[t0 * UU + um3] + s_lpl[t0 * UU + um2] + s_lpl[t0 * UU + um1];
        if (u < 1) B = NEGF;
        if (u < 2) C = NEGF;
        if (u < 3) D = NEGF;
        FW[j] = make_float4(A, B, C, D);
    }
    // ---- backward weights: j = m*64+u, m in [1,31]; cell t = 190-3m-u ----
    for (int j = 64 + tid; j < (SB3 + 1) * 64; j += DPT) {
        int m = j >> 6, u = j & 63;
        int t = 190 - 3 * m - u;
        float A, B, C, D;
        if (t > TT - 1) {                      // cell out-of-lattice: stays NEG
            A = B = C = D = NEGF;
        } else {
            int q0 = t;
            int q1 = min(t + 1, TT - 1);
            int q2 = min(t + 2, TT - 1);
            int u0 = u, u1 = min(u + 1, UU - 1), u2 = min(u + 2, UU - 1);

            float b00 = s_lpb[q0 * UU + u0], b01 = s_lpb[q0 * UU + u1], b02 = s_lpb[q0 * UU + u2];
            float b10 = s_lpb[q1 * UU + u0], b11 = s_lpb[q1 * UU + u1];
            float b20 = s_lpb[q2 * UU + u0];
            float l00 = s_lpl[q0 * UU + u0], l01 = s_lpl[q0 * UU + u1];
            float l10 = s_lpl[q1 * UU + u0], l11 = s_lpl[q1 * UU + u1];
            float l20 = s_lpl[q2 * UU + u0];

            A = b00 + b10 + b20;
            B = lae3(l00 + b01 + b11,
                     b00 + l10 + b11,
                     b00 + b10 + l20);
            C = lae3(b00 + l10 + l11,
                     l00 + b01 + l11,
                     l00 + l01 + b02);
            D = l00 + l01 + s_lpl[q0 * UU + u2];
            if (t + 3 > TT - 1)               A = NEGF;
            if (t + 2 > TT - 1 || u + 1 > 63) B = NEGF;
            if (t + 1 > TT - 1 || u + 2 > 63) C = NEGF;
            if (u + 3 > 63)                   D = NEGF;
        }
        BW[j] = make_float4(A, B, C, D);
    }
    __syncthreads();

    int wid = tid >> 5, lane = tid & 31;
    int u_lo = lane * 2;

    if (wid == 0) {
        // ---------------- forward: 32 super-steps ----------------
        float a_lo = (lane == 0) ? 0.f : NEGF;
        float a_hi = NEGF;
        float nh1 = __shfl_up_sync(0xffffffffu, a_hi, 1);
        float nl1 = __shfl_up_sync(0xffffffffu, a_lo, 1);
        float nh2 = __shfl_up_sync(0xffffffffu, a_hi, 2);
        int W = 64 + u_lo;
        float4 w0 = FW[W], w1 = FW[W + 1];

        for (int s = 1; s < SF3; s++) {
            float4 nw0 = FW[W + 64], nw1 = FW[W + 65];
            float n0 = lae4(a_lo + w0.x, nh1 + w0.y, nl1 + w0.z, nh2 + w0.w);
            float n1 = lae4(a_hi + w1.x, a_lo + w1.y, nh1 + w1.z, nl1 + w1.w);
            a_lo = n0; a_hi = n1;
            nh1 = __shfl_up_sync(0xffffffffu, a_hi, 1);
            nl1 = __shfl_up_sync(0xffffffffu, a_lo, 1);
            nh2 = __shfl_up_sync(0xffffffffu, a_hi, 2);
            w0 = nw0; w1 = nw1; W += 64;
        }
        {   // peel s = 32 (no trailing shfls)
            float n0 = lae4(a_lo + w0.x, nh1 + w0.y, nl1 + w0.z, nh2 + w0.w);
            float n1 = lae4(a_hi + w1.x, a_lo + w1.y, nh1 + w1.z, nl1 + w1.w);
            a_lo = n0; a_hi = n1;
        }
        s_meet[u_lo]     = a_lo;
        s_meet[u_lo + 1] = a_hi;
    } else if (wid == 1) {
        // ---------------- backward: 31 super-steps + 1 plain step ----------
        float b_lo = NEGF;
        float b_hi = (lane == 31) ? s_lpb[(TT - 1) * UU + (UU - 1)] : NEGF;
        float d1lo = __shfl_down_sync(0xffffffffu, b_lo, 1);
        float d1hi = __shfl_down_sync(0xffffffffu, b_hi, 1);
        float d2lo = __shfl_down_sync(0xffffffffu, b_lo, 2);
        int W = 64 + u_lo;
        float4 w0 = BW[W], w1 = BW[W + 1];

        for (int m = 1; m < SB3; m++) {
            float4 nw0 = BW[W + 64], nw1 = BW[W + 65];
            float n0 = lae4(b_lo + w0.x, b_hi + w0.y, d1lo + w0.z, d1hi + w0.w);
            float n1 = lae4(b_hi + w1.x, d1lo + w1.y, d1hi + w1.z, d2lo + w1.w);
            b_lo = n0; b_hi = n1;
            d1lo = __shfl_down_sync(0xffffffffu, b_lo, 1);
            d1hi = __shfl_down_sync(0xffffffffu, b_hi, 1);
            d2lo = __shfl_down_sync(0xffffffffu, b_lo, 2);
            w0 = nw0; w1 = nw1; W += 64;
        }
        {   // peel m = 31 -> beta on diag 97
            float n0 = lae4(b_lo + w0.x, b_hi + w0.y, d1lo + w0.z, d1hi + w0.w);
            float n1 = lae4(b_hi + w1.x, d1lo + w1.y, d1hi + w1.z, d2lo + w1.w);
            b_lo = n0; b_hi = n1;
        }
        // plain single-step 97 -> 96: beta[t,u] = LAE(lpb+beta[t+1,u], lpl+beta[t,u+1])
        {
            float nblo = __shfl_down_sync(0xffffffffu, b_lo, 1);   // beta97 at u_hi+1
            int tA = 96 - u_lo;            // cell (tA, u_lo), diag 96
            int tB = 96 - (u_lo + 1);      // cell (tB, u_hi)
            float lbA = s_lpb[tA * UU + u_lo];
            float llA = s_lpl[tA * UU + u_lo];            // u_lo <= 62 always
            float lbB = s_lpb[tB * UU + u_lo + 1];
            float t2B = (lane == 31) ? NEGF
                        : s_lpl[tB * UU + u_lo + 1] + nblo;   // u_hi<=62 when lane<31
            float n_lo = lae2(lbA + b_lo, llA + b_hi);
            float n_hi = lae2(lbB + b_hi, t2B);
            s_meet[128 + u_lo]     = n_lo;
            s_meet[128 + u_lo + 1] = n_hi;
        }
    }
    __syncthreads();

    // ---------------- combine on diag 96 + global mean ----------------
    if (wid == 0) {
        float v0 = s_meet[lane]      + s_meet[128 + lane];
        float v1 = s_meet[lane + 32] + s_meet[128 + lane + 32];
        float M = fmaxf(v0, v1);
#pragma unroll
        for (int o = 16; o; o >>= 1)
            M = fmaxf(M, __shfl_xor_sync(0xffffffffu, M, o));
        float e = fast_ex2(v0 - M) + fast_ex2(v1 - M);
#pragma unroll
        for (int o = 16; o; o >>= 1)
            e += __shfl_xor_sync(0xffffffffu, e, o);
        float ll2 = M + fast_lg2(e);           // log2-domain loglike

        int is_last = 0;
        if (lane == 0) {
            g_cost[b] = -ll2 * LN2F;
            __threadfence();
            is_last = (atomicAdd(&g_ticket, 1) == BB - 1);
        }
        is_last = __shfl_sync(0xffffffffu, is_last, 0);
        if (is_last) {
            float v = (lane < BB) ? __ldcg(&g_cost[lane]) : 0.f;
#pragma unroll
            for (int o = 16; o; o >>= 1)
                v += __shfl_xor_sync(0xffffffffu, v, o);
            if (lane == 0) {
                out[0] = v * (1.0f / BB);
                g_ticket = 0;                  // reset for next graph replay
            }
        }
    }
}

extern "C" void kernel_launch(void* const* d_in, const int* in_sizes, int n_in,
                              void* d_out, int out_size) {
    const float* acts   = (const float*)d_in[0];
    const int*   labels = (const int*)d_in[1];

    const int smem_bytes = 33280 * (int)sizeof(float);   // 133120
    cudaFuncSetAttribute(dp_kernel, cudaFuncAttributeMaxDynamicSharedMemorySize,
                         smem_bytes);

    lse_kernel<<<CELLS / 8, 256>>>(acts, labels);

    // PDL launch: dp blocks dispatch while lse streams; the in-kernel grid
    // dependency sync provides the ordering.
    cudaLaunchConfig_t cfg = {};
    cfg.gridDim         = dim3(BB, 1, 1);
    cfg.blockDim        = dim3(DPT, 1, 1);
    cfg.dynamicSmemBytes = smem_bytes;
    cfg.stream          = 0;
    cudaLaunchAttribute attr[1];
    attr[0].id = cudaLaunchAttributeProgrammaticStreamSerialization;
    attr[0].val.programmaticStreamSerializationAllowed = 1;
    cfg.attrs    = attr;
    cfg.numAttrs = 1;
    cudaLaunchKernelEx(&cfg, dp_kernel, (float*)d_out);
}